// round 14
// baseline (speedup 1.0000x reference)
#include <cuda_runtime.h>
#include <cstdint>

// PackedViterbi (logsumexp semiring) forward — dual chains per CTA.
// theta: [T=256, B=32, S=128, S=128] fp32.  out: [B=32] fp32.
//
// 16 clusters x 4 CTAs, 512 threads per CTA. Warps 0-7 run batch 2c (chain A),
// warps 8-15 run batch 2c+1 (chain B) — two fully independent R10 pipelines
// (own cp.async ring slots, own tagged log-domain DSMEM parity buffers, own
// 256-thread named barrier, own 4-rank fan-out). Each SMSP carries 2 A-warps
// + 2 B-warps, so one chain's transit/poll latency hides the other chain's
// exp2(theta) MUFU burst. Per-chain step logic is byte-for-byte R10.

#define NT   256
#define NB   32
#define NS   128
#define SUBS 4
#define NTC  256                     // threads per chain
#define NTHR 512
#define TILE_BYTES (32 * NS * 4)     // 16384 per chain-stage
#define PIPE 5
#define DIST 4
#define LOG2E 1.4426950408889634f
#define FULLM 0xffffffffu

static __device__ __forceinline__ float ex2f_(float x) {
    float y; asm("ex2.approx.ftz.f32 %0, %1;" : "=f"(y) : "f"(x)); return y;
}
static __device__ __forceinline__ float lg2f_(float x) {
    float y; asm("lg2.approx.ftz.f32 %0, %1;" : "=f"(y) : "f"(x)); return y;
}
static __device__ __forceinline__ void cp16(unsigned d, const void* s) {
    asm volatile("cp.async.cg.shared.global [%0], [%1], 16;" :: "r"(d), "l"(s));
}
static __device__ __forceinline__ void st_dsmem64(unsigned daddr, unsigned long long v) {
    asm volatile("st.relaxed.cluster.shared::cluster.b64 [%0], %1;"
                 :: "r"(daddr), "l"(v) : "memory");
}
static __device__ __forceinline__ unsigned long long ld_vol64(unsigned addr) {
    unsigned long long v;
    asm volatile("ld.volatile.shared.b64 %0, [%1];" : "=l"(v) : "r"(addr));
    return v;
}
static __device__ __forceinline__ void cbar(int g) {
    asm volatile("bar.sync %0, %1;" :: "r"(1 + g), "r"(NTC) : "memory");
}

extern "C" __global__ void __launch_bounds__(NTHR, 1) __cluster_dims__(SUBS, 1, 1)
viterbi_fwd(const float* __restrict__ theta, float* __restrict__ out)
{
    extern __shared__ float4 ring[];                           // 2*PIPE*TILE_BYTES
    __shared__ __align__(16) unsigned long long sV[2][2][NS];  // [chain][parity][j]
    __shared__ float sEV[2][2][NS];                            // exp2(V') tables

    const int tid   = threadIdx.x;
    const int lane  = tid & 31;
    const int warp  = tid >> 5;
    const int g     = warp >> 3;        // chain: 0 = warps 0-7, 1 = warps 8-15
    const int cwarp = warp & 7;
    const int ctid  = tid & 255;
    const int sl    = lane & 7;         // 8 lanes per row
    const int rg    = lane >> 3;
    const int rowL  = (cwarp << 2) + rg;       // local row 0..31
    const int bid   = blockIdx.x;
    const int sub   = bid & 3;                 // cluster rank
    const int bb    = (bid >> 2) * 2 + g;      // batch for this chain
    const int irow  = sub * 32 + rowL;

    unsigned rbase = (unsigned)__cvta_generic_to_shared(ring)
                   + (unsigned)(g * PIPE * TILE_BYTES);
    unsigned vbase = (unsigned)__cvta_generic_to_shared(&sV[0][0][0])
                   + (unsigned)(g * 2 * NS * 8);

    // zero all tags (512 threads, 512 slots)
    ((unsigned long long*)sV)[tid] = 0ull;
    __syncthreads();
    asm volatile("barrier.cluster.arrive.aligned;" ::: "memory");
    asm volatile("barrier.cluster.wait.aligned;"   ::: "memory");

    unsigned rV[SUBS];
#pragma unroll
    for (int r = 0; r < SUBS; ++r)
        asm("mapa.shared::cluster.u32 %0, %1, %2;" : "=r"(rV[r]) : "r"(vbase), "r"(r));

    const size_t tstride = (size_t)NB * NS * NS;
    const float* base = theta + ((size_t)bb * NS + (size_t)sub * 32) * NS;

    // ---- prologue: prefetch stages 0..DIST-1 for this chain ----
#pragma unroll
    for (int s = 0; s < DIST; ++s) {
        const char* src = (const char*)(base + (size_t)s * tstride);
        unsigned dst = rbase + (s % PIPE) * TILE_BYTES;
#pragma unroll
        for (int k2 = 0; k2 < 4; ++k2) {
            int o = (ctid + k2 * NTC) << 4;
            cp16(dst + o, src + o);
        }
        asm volatile("cp.async.commit_group;");
    }

    float Ea[16], Eb[16];
    float off = 0.f;

    // stage 0 -> Ea
    asm volatile("cp.async.wait_group 3;");
    cbar(g);                  // chain's stage-0 copies visible
    {
        const float4* tp = ring + (size_t)g * PIPE * (TILE_BYTES / 16)
                         + rowL * (NS / 4) + sl;
        float4 a0 = tp[0], a1 = tp[8], a2 = tp[16], a3 = tp[24];
        Ea[0]  = ex2f_(a0.x * LOG2E); Ea[1]  = ex2f_(a0.y * LOG2E);
        Ea[2]  = ex2f_(a0.z * LOG2E); Ea[3]  = ex2f_(a0.w * LOG2E);
        Ea[4]  = ex2f_(a1.x * LOG2E); Ea[5]  = ex2f_(a1.y * LOG2E);
        Ea[6]  = ex2f_(a1.z * LOG2E); Ea[7]  = ex2f_(a1.w * LOG2E);
        Ea[8]  = ex2f_(a2.x * LOG2E); Ea[9]  = ex2f_(a2.y * LOG2E);
        Ea[10] = ex2f_(a2.z * LOG2E); Ea[11] = ex2f_(a2.w * LOG2E);
        Ea[12] = ex2f_(a3.x * LOG2E); Ea[13] = ex2f_(a3.y * LOG2E);
        Ea[14] = ex2f_(a3.z * LOG2E); Ea[15] = ex2f_(a3.w * LOG2E);
    }

    auto step = [&](int t, int par, float (&Ecur)[16], float (&Enext)[16]) {
        // 1. ensure stage t+1 complete for this thread (<=2 groups pending)
        asm volatile("cp.async.wait_group 2;");

        // 2. poll V_t slot (one volatile LDS.64/thread), build exp2 entry
        float r;
        if (t == 0) {
            if (ctid < NS) sEV[g][0][ctid] = 1.f;
        } else {
            if (ctid < NS) {
                unsigned a = vbase + (unsigned)((par * NS + ctid) * 8);
                unsigned long long v;
                do { v = ld_vol64(a); } while ((unsigned)(v >> 32) != (unsigned)t);
                sEV[g][par][ctid] = ex2f_(__uint_as_float((unsigned)v));
            }
        }
        cbar(g);               // publishes sEV AND chain's stage-(t+1) copies
        r = (t > 0) ? __uint_as_float((unsigned)ld_vol64(
                          vbase + (unsigned)(par * NS * 8)))
                    : 0.f;
        off += r;

        // 3. dot product + 8-lane reduce
        const float4* evp = (const float4*)sEV[g][par];
        float4 e0 = evp[sl], e1 = evp[sl + 8], e2 = evp[sl + 16], e3 = evp[sl + 24];
        float s0 = Ecur[0] * e0.x;
        s0 = fmaf(Ecur[1],  e0.y, s0); s0 = fmaf(Ecur[2],  e0.z, s0); s0 = fmaf(Ecur[3],  e0.w, s0);
        float s1 = Ecur[4] * e1.x;
        s1 = fmaf(Ecur[5],  e1.y, s1); s1 = fmaf(Ecur[6],  e1.z, s1); s1 = fmaf(Ecur[7],  e1.w, s1);
        float s2 = Ecur[8] * e2.x;
        s2 = fmaf(Ecur[9],  e2.y, s2); s2 = fmaf(Ecur[10], e2.z, s2); s2 = fmaf(Ecur[11], e2.w, s2);
        float s3 = Ecur[12] * e3.x;
        s3 = fmaf(Ecur[13], e3.y, s3); s3 = fmaf(Ecur[14], e3.z, s3); s3 = fmaf(Ecur[15], e3.w, s3);
        float s = (s0 + s1) + (s2 + s3);
        s += __shfl_xor_sync(FULLM, s, 1);
        s += __shfl_xor_sync(FULLM, s, 2);
        s += __shfl_xor_sync(FULLM, s, 4);

        // 4. send V_{t+1} IMMEDIATELY (parallel 4-lane fan-out)
        float vst = lg2f_(s) - r;
        if (sl < SUBS) {
            unsigned long long pkt = ((unsigned long long)(unsigned)(t + 1) << 32)
                                   | (unsigned long long)__float_as_uint(vst);
            unsigned voff = (unsigned)((((t + 1) & 1) * NS + irow) * 8);
            st_dsmem64(rV[sl] + voff, pkt);
        }

        // 5. SHADOW WORK (overlaps DSMEM transit AND the other chain's poll):
        //    issue prefetch for t+DIST, then transform stage t+1 -> Enext
        if (t + DIST < NT) {
            const char* src = (const char*)(base + (size_t)(t + DIST) * tstride);
            unsigned dst = rbase + ((t + DIST) % PIPE) * TILE_BYTES;
#pragma unroll
            for (int k2 = 0; k2 < 4; ++k2) {
                int o = (ctid + k2 * NTC) << 4;
                cp16(dst + o, src + o);
            }
        }
        asm volatile("cp.async.commit_group;");

        if (t + 1 < NT) {
            const float4* tp = ring + (size_t)(g * PIPE + (t + 1) % PIPE) * (TILE_BYTES / 16)
                             + rowL * (NS / 4) + sl;
            float4 a0 = tp[0], a1 = tp[8], a2 = tp[16], a3 = tp[24];
            Enext[0]  = ex2f_(a0.x * LOG2E); Enext[1]  = ex2f_(a0.y * LOG2E);
            Enext[2]  = ex2f_(a0.z * LOG2E); Enext[3]  = ex2f_(a0.w * LOG2E);
            Enext[4]  = ex2f_(a1.x * LOG2E); Enext[5]  = ex2f_(a1.y * LOG2E);
            Enext[6]  = ex2f_(a1.z * LOG2E); Enext[7]  = ex2f_(a1.w * LOG2E);
            Enext[8]  = ex2f_(a2.x * LOG2E); Enext[9]  = ex2f_(a2.y * LOG2E);
            Enext[10] = ex2f_(a2.z * LOG2E); Enext[11] = ex2f_(a2.w * LOG2E);
            Enext[12] = ex2f_(a3.x * LOG2E); Enext[13] = ex2f_(a3.y * LOG2E);
            Enext[14] = ex2f_(a3.z * LOG2E); Enext[15] = ex2f_(a3.w * LOG2E);
        }
    };

    for (int t = 0; t < NT; t += 2) {
        step(t,     0, Ea, Eb);
        step(t + 1, 1, Eb, Ea);
    }

    // ---- epilogue: drain tag NT (parity 0), then rank 0 reduces per chain ----
    if (ctid < NS) {
        unsigned ad = vbase + (unsigned)(ctid * 8);
        unsigned long long v;
        do { v = ld_vol64(ad); } while ((unsigned)(v >> 32) != (unsigned)NT);
    }
    cbar(g);
    if (sub == 0 && cwarp == 0) {
        float x0 = __uint_as_float((unsigned)sV[g][0][lane]);
        float x1 = __uint_as_float((unsigned)sV[g][0][lane + 32]);
        float x2 = __uint_as_float((unsigned)sV[g][0][lane + 64]);
        float x3 = __uint_as_float((unsigned)sV[g][0][lane + 96]);
        float s = ex2f_(x0) + ex2f_(x1) + ex2f_(x2) + ex2f_(x3);
#pragma unroll
        for (int o = 16; o; o >>= 1) s += __shfl_xor_sync(FULLM, s, o);
        if (lane == 0)
            out[bb] = 0.6931471805599453f * (off + lg2f_(s));
    }
    __syncthreads();
    asm volatile("barrier.cluster.arrive.aligned;" ::: "memory");
    asm volatile("barrier.cluster.wait.aligned;"   ::: "memory");
}

extern "C" void kernel_launch(void* const* d_in, const int* in_sizes, int n_in,
                              void* d_out, int out_size)
{
    (void)in_sizes; (void)n_in; (void)out_size;
    const float* theta = (const float*)d_in[0];
    float* out = (float*)d_out;

    cudaFuncSetAttribute(viterbi_fwd,
                         cudaFuncAttributeMaxDynamicSharedMemorySize,
                         2 * PIPE * TILE_BYTES);
    viterbi_fwd<<<(NB / 2) * SUBS, NTHR, 2 * PIPE * TILE_BYTES>>>(theta, out);
}

// round 15
// speedup vs baseline: 1.4011x; 1.4011x over previous
#include <cuda_runtime.h>
#include <cuda_fp16.h>
#include <cstdint>

// PackedViterbi (logsumexp semiring) forward.
// theta: [T=256, B=32, S=128, S=128] fp32.  out: [B=32] fp32.
//
// R10 EXACTLY (32 clusters x 4 CTAs, 256 thr, tagged log-domain DSMEM relay,
// wait_group at top, poll -> syncthreads -> dot -> lg2 -> send -> shadow
// prefetch+transform) with the inner math moved to f16x2:
//   - transform: ex2.approx.f16x2 (2 values per MUFU op -> halves the
//     256-cyc/SMSP MUFU burst that was binding the step period)
//   - dot: 8 HFMA2 instead of 16 FFMA; exp(V) table stored as f16
//     (biased by 2^-18 for overflow headroom; all terms positive)
// Packets, renorm offset, epilogue stay fp32 log-domain.

#define NT   256
#define NB   32
#define NS   128
#define SUBS 4
#define RPC  32
#define NTHR 256
#define TILE_BYTES (RPC * NS * 4)    // 16384
#define PIPE 6
#define DIST 4
#define LOG2E 1.4426950408889634f
#define FULLM 0xffffffffu

static __device__ __forceinline__ float ex2f_(float x) {
    float y; asm("ex2.approx.ftz.f32 %0, %1;" : "=f"(y) : "f"(x)); return y;
}
static __device__ __forceinline__ float lg2f_(float x) {
    float y; asm("lg2.approx.ftz.f32 %0, %1;" : "=f"(y) : "f"(x)); return y;
}
static __device__ __forceinline__ void cp16(unsigned d, const void* s) {
    asm volatile("cp.async.cg.shared.global [%0], [%1], 16;" :: "r"(d), "l"(s));
}
static __device__ __forceinline__ void st_dsmem64(unsigned daddr, unsigned long long v) {
    asm volatile("st.relaxed.cluster.shared::cluster.b64 [%0], %1;"
                 :: "r"(daddr), "l"(v) : "memory");
}
static __device__ __forceinline__ unsigned long long ld_vol64(unsigned addr) {
    unsigned long long v;
    asm volatile("ld.volatile.shared.b64 %0, [%1];" : "=l"(v) : "r"(addr));
    return v;
}
// pack (lo,hi) -> f16x2, then ex2.approx.f16x2
static __device__ __forceinline__ unsigned ex2h2_(float lo, float hi) {
    unsigned h, r;
    asm("cvt.rn.f16x2.f32 %0, %1, %2;" : "=r"(h) : "f"(hi), "f"(lo));
    asm("ex2.approx.f16x2 %0, %1;" : "=r"(r) : "r"(h));
    return r;
}
static __device__ __forceinline__ unsigned hfma2_(unsigned a, unsigned b, unsigned c) {
    unsigned d;
    asm("fma.rn.f16x2 %0, %1, %2, %3;" : "=r"(d) : "r"(a), "r"(b), "r"(c));
    return d;
}
static __device__ __forceinline__ float2 h2f2_(unsigned h) {
    float lo, hi;
    asm("{\n\t.reg .f16 l, m;\n\tmov.b32 {l, m}, %2;\n\t"
        "cvt.f32.f16 %0, l;\n\tcvt.f32.f16 %1, m;\n\t}"
        : "=f"(lo), "=f"(hi) : "r"(h));
    return make_float2(lo, hi);
}

extern "C" __global__ void __launch_bounds__(NTHR, 1) __cluster_dims__(SUBS, 1, 1)
viterbi_fwd(const float* __restrict__ theta, float* __restrict__ out)
{
    extern __shared__ float4 ring[];                         // PIPE * 1024 float4
    __shared__ __align__(16) unsigned long long sV[2][NS];   // tagged V' packets (fp32 log)
    __shared__ __align__(8) __half sEVh[2][NS];              // exp2(V' - 18) tables, f16

    const int tid  = threadIdx.x;
    const int lane = tid & 31;
    const int warp = tid >> 5;
    const int sl   = lane & 7;          // 8 lanes per row
    const int rg   = lane >> 3;
    const int rowL = (warp << 2) + rg;  // local row 0..31
    const int bid  = blockIdx.x;
    const int bb   = bid >> 2;          // batch
    const int sub  = bid & 3;           // cluster rank
    const int irow = sub * RPC + rowL;  // global state index i

    unsigned rbase = (unsigned)__cvta_generic_to_shared(ring);
    unsigned vbase = (unsigned)__cvta_generic_to_shared(&sV[0][0]);

    // zero tags before any peer can write
    ((unsigned long long*)sV)[tid] = 0ull;
    __syncthreads();
    asm volatile("barrier.cluster.arrive.aligned;" ::: "memory");
    asm volatile("barrier.cluster.wait.aligned;"   ::: "memory");

    unsigned rV[SUBS];
#pragma unroll
    for (int r = 0; r < SUBS; ++r)
        asm("mapa.shared::cluster.u32 %0, %1, %2;" : "=r"(rV[r]) : "r"(vbase), "r"(r));

    const size_t tstride = (size_t)NB * NS * NS;
    const float* base = theta + ((size_t)bb * NS + (size_t)sub * RPC) * NS;

    // ---- prologue: prefetch stages 0..DIST-1 ----
#pragma unroll
    for (int s = 0; s < DIST; ++s) {
        const char* src = (const char*)(base + (size_t)s * tstride);
        unsigned dst = rbase + s * TILE_BYTES;
#pragma unroll
        for (int k2 = 0; k2 < 4; ++k2) {
            int o = (tid + k2 * NTHR) << 4;
            cp16(dst + o, src + o);
        }
        asm volatile("cp.async.commit_group;");
    }

    unsigned Ea[8], Eb[8];     // f16x2 pairs: E[2k]=(j,j+1), E[2k+1]=(j+2,j+3), j=32k+4sl
    float off = 0.f;

    // stage 0 -> Ea
    asm volatile("cp.async.wait_group 3;");
    __syncthreads();          // all warps' stage-0 copies visible
    {
        const float4* tp = ring + rowL * (NS / 4) + sl;
        float4 a0 = tp[0], a1 = tp[8], a2 = tp[16], a3 = tp[24];
        Ea[0] = ex2h2_(a0.x * LOG2E, a0.y * LOG2E);
        Ea[1] = ex2h2_(a0.z * LOG2E, a0.w * LOG2E);
        Ea[2] = ex2h2_(a1.x * LOG2E, a1.y * LOG2E);
        Ea[3] = ex2h2_(a1.z * LOG2E, a1.w * LOG2E);
        Ea[4] = ex2h2_(a2.x * LOG2E, a2.y * LOG2E);
        Ea[5] = ex2h2_(a2.z * LOG2E, a2.w * LOG2E);
        Ea[6] = ex2h2_(a3.x * LOG2E, a3.y * LOG2E);
        Ea[7] = ex2h2_(a3.z * LOG2E, a3.w * LOG2E);
    }

    auto step = [&](int t, int par, unsigned (&Ecur)[8], unsigned (&Enext)[8]) {
        // 1. ensure stage t+1 complete for this thread (<=2 groups pending)
        asm volatile("cp.async.wait_group 2;");

        // 2. poll V_t slot (one volatile LDS.64/thread), build f16 exp2 entry
        float r;
        if (t == 0) {
            if (tid < NS) sEVh[0][tid] = __float2half_rn(3.814697265625e-06f); // 2^-18
        } else {
            if (tid < NS) {
                unsigned a = vbase + (unsigned)((par * NS + tid) * 8);
                unsigned long long v;
                do { v = ld_vol64(a); } while ((unsigned)(v >> 32) != (unsigned)t);
                sEVh[par][tid] =
                    __float2half_rn(ex2f_(__uint_as_float((unsigned)v) - 18.f));
            }
        }
        __syncthreads();       // publishes table AND all warps' stage-(t+1) copies
        r = (t > 0) ? __uint_as_float((unsigned)ld_vol64(
                          vbase + (unsigned)(par * NS * 8)))
                    : 0.f;
        off += r;

        // 3. f16x2 dot (8 HFMA2) + 8-lane reduce
        const __half* tb = sEVh[par];
        uint2 w0 = *(const uint2*)(tb + 4 * sl);
        uint2 w1 = *(const uint2*)(tb + 32 + 4 * sl);
        uint2 w2 = *(const uint2*)(tb + 64 + 4 * sl);
        uint2 w3 = *(const uint2*)(tb + 96 + 4 * sl);
        unsigned acc0 = 0u, acc1 = 0u;
        acc0 = hfma2_(Ecur[0], w0.x, acc0); acc1 = hfma2_(Ecur[1], w0.y, acc1);
        acc0 = hfma2_(Ecur[2], w1.x, acc0); acc1 = hfma2_(Ecur[3], w1.y, acc1);
        acc0 = hfma2_(Ecur[4], w2.x, acc0); acc1 = hfma2_(Ecur[5], w2.y, acc1);
        acc0 = hfma2_(Ecur[6], w3.x, acc0); acc1 = hfma2_(Ecur[7], w3.y, acc1);
        float2 f0 = h2f2_(acc0), f1 = h2f2_(acc1);
        float s = (f0.x + f0.y) + (f1.x + f1.y);
        s += __shfl_xor_sync(FULLM, s, 1);
        s += __shfl_xor_sync(FULLM, s, 2);
        s += __shfl_xor_sync(FULLM, s, 4);

        // 4. send V_{t+1} IMMEDIATELY (parallel 4-lane fan-out)
        float vst = lg2f_(s) + 18.f - r;     // undo table bias
        if (sl < SUBS) {
            unsigned long long pkt = ((unsigned long long)(unsigned)(t + 1) << 32)
                                   | (unsigned long long)__float_as_uint(vst);
            unsigned voff = (unsigned)((((t + 1) & 1) * NS + irow) * 8);
            st_dsmem64(rV[sl] + voff, pkt);
        }

        // 5. SHADOW WORK (overlaps the DSMEM transit of V_{t+1}):
        //    issue prefetch for t+DIST, then transform stage t+1 -> Enext
        if (t + DIST < NT) {
            const char* src = (const char*)(base + (size_t)(t + DIST) * tstride);
            unsigned dst = rbase + ((t + DIST) % PIPE) * TILE_BYTES;
#pragma unroll
            for (int k2 = 0; k2 < 4; ++k2) {
                int o = (tid + k2 * NTHR) << 4;
                cp16(dst + o, src + o);
            }
        }
        asm volatile("cp.async.commit_group;");

        if (t + 1 < NT) {
            const float4* tp = ring + ((t + 1) % PIPE) * (TILE_BYTES / 16)
                             + rowL * (NS / 4) + sl;
            float4 a0 = tp[0], a1 = tp[8], a2 = tp[16], a3 = tp[24];
            Enext[0] = ex2h2_(a0.x * LOG2E, a0.y * LOG2E);
            Enext[1] = ex2h2_(a0.z * LOG2E, a0.w * LOG2E);
            Enext[2] = ex2h2_(a1.x * LOG2E, a1.y * LOG2E);
            Enext[3] = ex2h2_(a1.z * LOG2E, a1.w * LOG2E);
            Enext[4] = ex2h2_(a2.x * LOG2E, a2.y * LOG2E);
            Enext[5] = ex2h2_(a2.z * LOG2E, a2.w * LOG2E);
            Enext[6] = ex2h2_(a3.x * LOG2E, a3.y * LOG2E);
            Enext[7] = ex2h2_(a3.z * LOG2E, a3.w * LOG2E);
        }
    };

    for (int t = 0; t < NT; t += 2) {
        step(t,     0, Ea, Eb);
        step(t + 1, 1, Eb, Ea);
    }

    // ---- epilogue: drain tag NT (parity 0), then rank 0 reduces (fp32) ----
    if (tid < NS) {
        unsigned ad = vbase + (unsigned)(tid * 8);
        unsigned long long v;
        do { v = ld_vol64(ad); } while ((unsigned)(v >> 32) != (unsigned)NT);
    }
    __syncthreads();
    if (sub == 0 && warp == 0) {
        float x0 = __uint_as_float((unsigned)sV[0][lane]);
        float x1 = __uint_as_float((unsigned)sV[0][lane + 32]);
        float x2 = __uint_as_float((unsigned)sV[0][lane + 64]);
        float x3 = __uint_as_float((unsigned)sV[0][lane + 96]);
        float s = ex2f_(x0) + ex2f_(x1) + ex2f_(x2) + ex2f_(x3);
#pragma unroll
        for (int o = 16; o; o >>= 1) s += __shfl_xor_sync(FULLM, s, o);
        if (lane == 0)
            out[bb] = 0.6931471805599453f * (off + lg2f_(s));
    }
    asm volatile("barrier.cluster.arrive.aligned;" ::: "memory");
    asm volatile("barrier.cluster.wait.aligned;"   ::: "memory");
}

extern "C" void kernel_launch(void* const* d_in, const int* in_sizes, int n_in,
                              void* d_out, int out_size)
{
    (void)in_sizes; (void)n_in; (void)out_size;
    const float* theta = (const float*)d_in[0];
    float* out = (float*)d_out;

    cudaFuncSetAttribute(viterbi_fwd,
                         cudaFuncAttributeMaxDynamicSharedMemorySize,
                         PIPE * TILE_BYTES);
    viterbi_fwd<<<NB * SUBS, NTHR, PIPE * TILE_BYTES>>>(theta, out);
}